// round 12
// baseline (speedup 1.0000x reference)
#include <cuda_runtime.h>
#include <cuda_fp16.h>
#include <cstdint>

#define THREADS 512
#define NCONS 384                      // 12 consumer warps
#define ROWS 96                        // tokens per tile
#define SCALE 0.0048957583488887505f   // sqrt(pi/2)/256
#define TAU 2e-2f

// smem layout (bytes). Row pitch 272B = 136 halves (conflict-free ldmatrix).
#define EST_OFF 0                      // float[96][4]
#define BUF_OFF 2048                   // 2 x (K 26112 + Q 26112)
#define BUF_SZ  52224
#define S_OFF   (BUF_OFF + 2 * BUF_SZ) // 106496; S: 256 x 272
#define SMEM_TOTAL (S_OFF + 69632)     // 176128

__device__ __align__(16) unsigned char g_Sfp16[69632];

__device__ __forceinline__ uint32_t smem_u32(const void* p) {
    uint32_t a;
    asm("{ .reg .u64 t; cvta.to.shared.u64 t, %1; cvt.u32.u64 %0, t; }"
        : "=r"(a) : "l"(p));
    return a;
}
__device__ __forceinline__ uint32_t f16x2(float lo, float hi) {
    uint32_t r;
    asm("cvt.rn.f16x2.f32 %0, %1, %2;" : "=r"(r) : "f"(hi), "f"(lo));
    return r;
}
__device__ __forceinline__ void ldsm_x4(uint32_t* r, uint32_t a) {
    asm volatile("ldmatrix.sync.aligned.m8n8.x4.shared.b16 {%0,%1,%2,%3}, [%4];"
                 : "=r"(r[0]), "=r"(r[1]), "=r"(r[2]), "=r"(r[3]) : "r"(a));
}
__device__ __forceinline__ void mma16816(float* d, const uint32_t* a,
                                         uint32_t b0, uint32_t b1) {
    asm volatile(
        "mma.sync.aligned.m16n8k16.row.col.f32.f16.f16.f32 "
        "{%0,%1,%2,%3}, {%4,%5,%6,%7}, {%8,%9}, {%0,%1,%2,%3};"
        : "+f"(d[0]), "+f"(d[1]), "+f"(d[2]), "+f"(d[3])
        : "r"(a[0]), "r"(a[1]), "r"(a[2]), "r"(a[3]), "r"(b0), "r"(b1));
}
__device__ __forceinline__ void cp16(uint32_t saddr, const void* gaddr) {
    asm volatile("cp.async.cg.shared.global [%0], [%1], 16;"
                 :: "r"(saddr), "l"(gaddr) : "memory");
}

// ---------------------------------------------------------------------------
// Kernel 0: convert S (256x128 fp32) -> fp16 image with 272B row pitch.
// ---------------------------------------------------------------------------
__global__ void qjl_conv_S(const float* __restrict__ S) {
    int i = blockIdx.x * blockDim.x + threadIdx.x;  // 0..4095
    int row = i >> 4, g = i & 15;
    const float4* src = (const float4*)(S + (size_t)row * 128 + g * 8);
    float4 a = __ldg(src), b = __ldg(src + 1);
    uint4 o;
    o.x = f16x2(a.x, a.y); o.y = f16x2(a.z, a.w);
    o.z = f16x2(b.x, b.y); o.w = f16x2(b.z, b.w);
    *(uint4*)(g_Sfp16 + row * 272 + g * 16) = o;
}

// stage one 96-token tile of k,q (fp32 -> fp16) with 128 producer threads
__device__ __forceinline__ void stage_tile(char* smem, uint32_t koff, uint32_t qoff,
                                           const float* __restrict__ key,
                                           const float* __restrict__ qry,
                                           int tok_base, int ntok, int ptid) {
    if (tok_base + ROWS <= ntok) {
        const float4* kg = (const float4*)(key + (size_t)tok_base * 128);
        const float4* qg = (const float4*)(qry + (size_t)tok_base * 128);
        #pragma unroll
        for (int it = 0; it < (ROWS * 32) / 128; it++) {
            int u = ptid + it * 128;
            uint32_t doff = (uint32_t)(u >> 5) * 272 + (uint32_t)(u & 31) * 8;
            float4 v = __ldg(kg + u);
            uint2 pk; pk.x = f16x2(v.x, v.y); pk.y = f16x2(v.z, v.w);
            *(uint2*)(smem + koff + doff) = pk;
            float4 w = __ldg(qg + u);
            uint2 pq; pq.x = f16x2(w.x, w.y); pq.y = f16x2(w.z, w.w);
            *(uint2*)(smem + qoff + doff) = pq;
        }
    } else {
        for (int u = ptid; u < ROWS * 32; u += 128) {
            int row = u >> 5, c4 = u & 31;
            int tok = tok_base + row; if (tok >= ntok) tok = ntok - 1;
            uint32_t doff = (uint32_t)row * 272 + (uint32_t)c4 * 8;
            float4 v = __ldg((const float4*)(key + (size_t)tok * 128) + c4);
            uint2 pk; pk.x = f16x2(v.x, v.y); pk.y = f16x2(v.z, v.w);
            *(uint2*)(smem + koff + doff) = pk;
            float4 w = __ldg((const float4*)(qry + (size_t)tok * 128) + c4);
            uint2 pq; pq.x = f16x2(w.x, w.y); pq.y = f16x2(w.z, w.w);
            *(uint2*)(smem + qoff + doff) = pq;
        }
    }
}

// Software-pipelined GEMM pass: 32x64 warp tile, frags double-buffered so
// ldsm(ks+1) overlaps mma(ks). Regs: acc 64 + A 16 + B 32 = 112.
__device__ __forceinline__ void pass_pipe(uint32_t a_addr, uint32_t b_addr,
                                          float (&acc)[2][8][4]) {
    uint32_t A0[2][4], A1[2][4], B[2][4][4];
    ldsm_x4(A0[0], a_addr);
    ldsm_x4(A1[0], a_addr + 16 * 272);
    #pragma unroll
    for (int g = 0; g < 4; g++)
        ldsm_x4(B[0][g], b_addr + g * (16 * 272));
    #pragma unroll
    for (int ks = 0; ks < 8; ks++) {
        const int cur = ks & 1, nxt = cur ^ 1;
        if (ks < 7) {
            uint32_t an = a_addr + (ks + 1) * 32;
            ldsm_x4(A0[nxt], an);
            ldsm_x4(A1[nxt], an + 16 * 272);
            #pragma unroll
            for (int g = 0; g < 4; g++)
                ldsm_x4(B[nxt][g], b_addr + g * (16 * 272) + (ks + 1) * 32);
        }
        #pragma unroll
        for (int g = 0; g < 4; g++) {
            mma16816(acc[0][2 * g],     A0[cur], B[cur][g][0], B[cur][g][1]);
            mma16816(acc[1][2 * g],     A1[cur], B[cur][g][0], B[cur][g][1]);
            mma16816(acc[0][2 * g + 1], A0[cur], B[cur][g][2], B[cur][g][3]);
            mma16816(acc[1][2 * g + 1], A1[cur], B[cur][g][2], B[cur][g][3]);
        }
    }
}

// ---------------------------------------------------------------------------
// Main kernel: persistent, 1 CTA/SM. 12 consumer warps (3Mx4N, 32x64 tiles)
// compute tile i while 4 producer warps stage tile i+1 (double-buffered).
// ---------------------------------------------------------------------------
__global__ void __launch_bounds__(THREADS, 1)
qjl_fused(const float* __restrict__ qry, const float* __restrict__ key,
          const float* __restrict__ Sg, float* __restrict__ out,
          int ntok, int ntiles) {
    extern __shared__ char smem[];
    const uint32_t sb = smem_u32(smem);
    const int tid = threadIdx.x, wid = tid >> 5, l = tid & 31;
    const bool producer = (wid >= 12);
    const int ptid = tid - NCONS;

    // ---- S image -> smem (all threads, async) ----
    for (int u = tid; u < 4352; u += THREADS)
        cp16(sb + S_OFF + u * 16, g_Sfp16 + u * 16);
    asm volatile("cp.async.commit_group;" ::: "memory");

    // ---- prologue: producers stage first tile into buffer 0 ----
    if (producer)
        stage_tile(smem, BUF_OFF, BUF_OFF + 26112, key, qry,
                   blockIdx.x * ROWS, ntok, ptid);
    asm volatile("cp.async.wait_group 0;" ::: "memory");
    __syncthreads();

    const int wm = wid >> 2, wn = wid & 3;   // consumers: wm 0..2, wn 0..3
    const uint32_t a_base = (uint32_t)wm * (32 * 272)
                          + (uint32_t)(l & 15) * 272 + (uint32_t)(l >> 4) * 16;
    const uint32_t b_base = sb + S_OFF + (uint32_t)wn * (64 * 272)
                          + (uint32_t)(l >> 4) * (8 * 272)
                          + (uint32_t)(l & 7) * 272 + (uint32_t)((l >> 3) & 1) * 16;

    int parity = 0;
    for (int tile = blockIdx.x; tile < ntiles; tile += gridDim.x, parity ^= 1) {
        const int tok_base = tile * ROWS;

        if (producer) {
            int nt_tile = tile + gridDim.x;
            if (nt_tile < ntiles)
                stage_tile(smem, BUF_OFF + (parity ^ 1) * BUF_SZ,
                           BUF_OFF + (parity ^ 1) * BUF_SZ + 26112,
                           key, qry, nt_tile * ROWS, ntok, ptid);
        } else {
            const uint32_t koff = BUF_OFF + parity * BUF_SZ;
            const uint32_t qoff = koff + 26112;

            float acc[2][8][4];
            #pragma unroll
            for (int mt = 0; mt < 2; mt++)
                #pragma unroll
                for (int nt = 0; nt < 8; nt++)
                    #pragma unroll
                    for (int j = 0; j < 4; j++) acc[mt][nt][j] = 0.f;

            // ---- k-projection (pipelined) ----
            pass_pipe(sb + koff + a_base, b_base, acc);

            // ---- signs + near-zero flags ----
            unsigned long long sign = 0ull, flag = 0ull;
            #pragma unroll
            for (int mt = 0; mt < 2; mt++)
                #pragma unroll
                for (int nt = 0; nt < 8; nt++)
                    #pragma unroll
                    for (int j = 0; j < 4; j++) {
                        int id = mt * 32 + nt * 4 + j;
                        float v = acc[mt][nt][j];
                        if (v > 0.f) sign |= 1ull << id;
                        if (fabsf(v) < TAU) flag |= 1ull << id;
                    }

            // ---- warp-cooperative exact fp32 fixup ----
            for (;;) {
                uint32_t active = __ballot_sync(0xFFFFFFFFu, flag != 0ull);
                if (!active) break;
                int leader = __ffs(active) - 1;
                int tok = 0, proj = 0, id = 0;
                if (l == leader) {
                    id = __ffsll(flag) - 1;
                    int mt = id >> 5, j = id & 3;
                    int nt = (id >> 2) & 7;
                    int row = wm * 32 + mt * 16 + (l >> 2) + (j >> 1) * 8;
                    tok = tok_base + row; if (tok >= ntok) tok = ntok - 1;
                    proj = wn * 64 + nt * 8 + (l & 3) * 2 + (j & 1);
                }
                tok  = __shfl_sync(0xFFFFFFFFu, tok, leader);
                proj = __shfl_sync(0xFFFFFFFFu, proj, leader);
                const float* kr = key + (size_t)tok * 128 + l * 4;
                const float* sr = Sg + (size_t)proj * 128 + l * 4;
                float p = 0.f;
                #pragma unroll
                for (int d = 0; d < 4; d++) p = fmaf(__ldg(kr + d), __ldg(sr + d), p);
                #pragma unroll
                for (int off = 16; off > 0; off >>= 1)
                    p += __shfl_xor_sync(0xFFFFFFFFu, p, off);
                if (l == leader) {
                    unsigned long long b = 1ull << id;
                    if (p > 0.f) sign |= b; else sign &= ~b;
                    flag &= flag - 1;
                }
            }

            // ---- q-projection (pipelined) ----
            #pragma unroll
            for (int mt = 0; mt < 2; mt++)
                #pragma unroll
                for (int nt = 0; nt < 8; nt++)
                    #pragma unroll
                    for (int j = 0; j < 4; j++) acc[mt][nt][j] = 0.f;
            pass_pipe(sb + qoff + a_base, b_base, acc);

            // ---- epilogue: signed reduction, consumer-only barrier ----
            float* est = (float*)smem;   // [96][4]
            #pragma unroll
            for (int mt = 0; mt < 2; mt++)
                #pragma unroll
                for (int h = 0; h < 2; h++) {
                    float s = 0.f;
                    #pragma unroll
                    for (int nt = 0; nt < 8; nt++)
                        #pragma unroll
                        for (int jj = 0; jj < 2; jj++) {
                            int j = h * 2 + jj;
                            int id = mt * 32 + nt * 4 + j;
                            float v = acc[mt][nt][j];
                            s += ((sign >> id) & 1ull) ? v : -v;
                        }
                    s += __shfl_xor_sync(0xFFFFFFFFu, s, 1);
                    s += __shfl_xor_sync(0xFFFFFFFFu, s, 2);
                    if ((l & 3) == 0) {
                        int row = wm * 32 + mt * 16 + h * 8 + (l >> 2);
                        est[row * 4 + wn] = s;
                    }
                }
            asm volatile("bar.sync 1, %0;" :: "n"(NCONS) : "memory");
            if (tid < ROWS) {
                int tok = tok_base + tid;
                if (tok < ntok) {
                    const float* e = est + tid * 4;
                    out[tok] = SCALE * ((e[0] + e[1]) + (e[2] + e[3]));
                }
            }
        }
        __syncthreads();   // seal staged buffer / release est for next tile
    }
}

extern "C" void kernel_launch(void* const* d_in, const int* in_sizes, int n_in,
                              void* d_out, int out_size) {
    const float* q = (const float*)d_in[0];
    const float* k = (const float*)d_in[1];
    const float* S = (const float*)d_in[2];
    float* out = (float*)d_out;

    int ntok = in_sizes[0] / 128;
    int ntiles = (ntok + ROWS - 1) / ROWS;
    int grid = ntiles < 148 ? ntiles : 148;

    qjl_conv_S<<<16, 256>>>(S);

    cudaFuncSetAttribute(qjl_fused, cudaFuncAttributeMaxDynamicSharedMemorySize,
                         SMEM_TOTAL);
    qjl_fused<<<grid, THREADS, SMEM_TOTAL>>>(q, k, S, out, ntok, ntiles);
}

// round 13
// speedup vs baseline: 1.0054x; 1.0054x over previous
#include <cuda_runtime.h>
#include <cuda_fp16.h>
#include <cstdint>

#define THREADS 512
#define NCONS 384                      // 12 consumer warps
#define ROWS 96                        // tokens per tile
#define SCALE 0.0048957583488887505f   // sqrt(pi/2)/256
#define TAU 2e-2f

// smem layout (bytes). Row pitch 272B = 136 halves (conflict-free ldmatrix).
#define EST_OFF 0                      // float[96][4]
#define BUF_OFF 2048                   // 2 x (K 26112 + Q 26112)
#define BUF_SZ  52224
#define S_OFF   (BUF_OFF + 2 * BUF_SZ) // 106496; S: 256 x 272
#define SMEM_TOTAL (S_OFF + 69632)     // 176128

__device__ __align__(16) unsigned char g_Sfp16[69632];

__device__ __forceinline__ uint32_t smem_u32(const void* p) {
    uint32_t a;
    asm("{ .reg .u64 t; cvta.to.shared.u64 t, %1; cvt.u32.u64 %0, t; }"
        : "=r"(a) : "l"(p));
    return a;
}
__device__ __forceinline__ uint32_t f16x2(float lo, float hi) {
    uint32_t r;
    asm("cvt.rn.f16x2.f32 %0, %1, %2;" : "=r"(r) : "f"(hi), "f"(lo));
    return r;
}
__device__ __forceinline__ void ldsm_x4(uint32_t* r, uint32_t a) {
    asm volatile("ldmatrix.sync.aligned.m8n8.x4.shared.b16 {%0,%1,%2,%3}, [%4];"
                 : "=r"(r[0]), "=r"(r[1]), "=r"(r[2]), "=r"(r[3]) : "r"(a));
}
__device__ __forceinline__ void mma16816(float* d, const uint32_t* a,
                                         uint32_t b0, uint32_t b1) {
    asm volatile(
        "mma.sync.aligned.m16n8k16.row.col.f32.f16.f16.f32 "
        "{%0,%1,%2,%3}, {%4,%5,%6,%7}, {%8,%9}, {%0,%1,%2,%3};"
        : "+f"(d[0]), "+f"(d[1]), "+f"(d[2]), "+f"(d[3])
        : "r"(a[0]), "r"(a[1]), "r"(a[2]), "r"(a[3]), "r"(b0), "r"(b1));
}
__device__ __forceinline__ void cp16(uint32_t saddr, const void* gaddr) {
    asm volatile("cp.async.cg.shared.global [%0], [%1], 16;"
                 :: "r"(saddr), "l"(gaddr) : "memory");
}

// ---------------------------------------------------------------------------
// Kernel 0: convert S (256x128 fp32) -> fp16 image with 272B row pitch.
// ---------------------------------------------------------------------------
__global__ void qjl_conv_S(const float* __restrict__ S) {
    int i = blockIdx.x * blockDim.x + threadIdx.x;  // 0..4095
    int row = i >> 4, g = i & 15;
    const float4* src = (const float4*)(S + (size_t)row * 128 + g * 8);
    float4 a = __ldg(src), b = __ldg(src + 1);
    uint4 o;
    o.x = f16x2(a.x, a.y); o.y = f16x2(a.z, a.w);
    o.z = f16x2(b.x, b.y); o.w = f16x2(b.z, b.w);
    *(uint4*)(g_Sfp16 + row * 272 + g * 16) = o;
}

// stage one 96-token tile of k,q (fp32 -> fp16) with 128 producer threads
__device__ __forceinline__ void stage_tile(char* smem, uint32_t koff, uint32_t qoff,
                                           const float* __restrict__ key,
                                           const float* __restrict__ qry,
                                           int tok_base, int ntok, int ptid) {
    if (tok_base + ROWS <= ntok) {
        const float4* kg = (const float4*)(key + (size_t)tok_base * 128);
        const float4* qg = (const float4*)(qry + (size_t)tok_base * 128);
        #pragma unroll
        for (int it = 0; it < (ROWS * 32) / 128; it++) {
            int u = ptid + it * 128;
            uint32_t doff = (uint32_t)(u >> 5) * 272 + (uint32_t)(u & 31) * 8;
            float4 v = __ldg(kg + u);
            uint2 pk; pk.x = f16x2(v.x, v.y); pk.y = f16x2(v.z, v.w);
            *(uint2*)(smem + koff + doff) = pk;
            float4 w = __ldg(qg + u);
            uint2 pq; pq.x = f16x2(w.x, w.y); pq.y = f16x2(w.z, w.w);
            *(uint2*)(smem + qoff + doff) = pq;
        }
    } else {
        for (int u = ptid; u < ROWS * 32; u += 128) {
            int row = u >> 5, c4 = u & 31;
            int tok = tok_base + row; if (tok >= ntok) tok = ntok - 1;
            uint32_t doff = (uint32_t)row * 272 + (uint32_t)c4 * 8;
            float4 v = __ldg((const float4*)(key + (size_t)tok * 128) + c4);
            uint2 pk; pk.x = f16x2(v.x, v.y); pk.y = f16x2(v.z, v.w);
            *(uint2*)(smem + koff + doff) = pk;
            float4 w = __ldg((const float4*)(qry + (size_t)tok * 128) + c4);
            uint2 pq; pq.x = f16x2(w.x, w.y); pq.y = f16x2(w.z, w.w);
            *(uint2*)(smem + qoff + doff) = pq;
        }
    }
}

// Software-pipelined GEMM pass, register-budgeted: B double-buffered
// (prefetch B(ks+1) before the mma burst of ks), A single-buffered.
// Live regs: acc 64 + B 32 + A 8 = 104.
__device__ __forceinline__ void pass_pipe(uint32_t a_addr, uint32_t b_addr,
                                          float (&acc)[2][8][4]) {
    uint32_t Be[4][4], Bo[4][4];   // even/odd ks buffers
    #pragma unroll
    for (int g = 0; g < 4; g++)
        ldsm_x4(Be[g], b_addr + g * (16 * 272));
    #pragma unroll
    for (int ks = 0; ks < 8; ks++) {
        uint32_t A0[4], A1[4];
        ldsm_x4(A0, a_addr + ks * 32);
        ldsm_x4(A1, a_addr + ks * 32 + 16 * 272);
        if ((ks & 1) == 0) {
            if (ks < 7) {
                #pragma unroll
                for (int g = 0; g < 4; g++)
                    ldsm_x4(Bo[g], b_addr + g * (16 * 272) + (ks + 1) * 32);
            }
            #pragma unroll
            for (int g = 0; g < 4; g++) {
                mma16816(acc[0][2 * g],     A0, Be[g][0], Be[g][1]);
                mma16816(acc[1][2 * g],     A1, Be[g][0], Be[g][1]);
                mma16816(acc[0][2 * g + 1], A0, Be[g][2], Be[g][3]);
                mma16816(acc[1][2 * g + 1], A1, Be[g][2], Be[g][3]);
            }
        } else {
            if (ks < 7) {
                #pragma unroll
                for (int g = 0; g < 4; g++)
                    ldsm_x4(Be[g], b_addr + g * (16 * 272) + (ks + 1) * 32);
            }
            #pragma unroll
            for (int g = 0; g < 4; g++) {
                mma16816(acc[0][2 * g],     A0, Bo[g][0], Bo[g][1]);
                mma16816(acc[1][2 * g],     A1, Bo[g][0], Bo[g][1]);
                mma16816(acc[0][2 * g + 1], A0, Bo[g][2], Bo[g][3]);
                mma16816(acc[1][2 * g + 1], A1, Bo[g][2], Bo[g][3]);
            }
        }
    }
}

// ---------------------------------------------------------------------------
// Main kernel: persistent, 1 CTA/SM. 12 consumer warps (3Mx4N, 32x64 tiles)
// compute tile i while 4 producer warps stage tile i+1 (double-buffered).
// ---------------------------------------------------------------------------
__global__ void __launch_bounds__(THREADS, 1)
qjl_fused(const float* __restrict__ qry, const float* __restrict__ key,
          const float* __restrict__ Sg, float* __restrict__ out,
          int ntok, int ntiles) {
    extern __shared__ char smem[];
    const uint32_t sb = smem_u32(smem);
    const int tid = threadIdx.x, wid = tid >> 5, l = tid & 31;
    const bool producer = (wid >= 12);
    const int ptid = tid - NCONS;

    // ---- S image -> smem (all threads, async) ----
    for (int u = tid; u < 4352; u += THREADS)
        cp16(sb + S_OFF + u * 16, g_Sfp16 + u * 16);
    asm volatile("cp.async.commit_group;" ::: "memory");

    // ---- prologue: producers stage first tile into buffer 0 ----
    if (producer)
        stage_tile(smem, BUF_OFF, BUF_OFF + 26112, key, qry,
                   blockIdx.x * ROWS, ntok, ptid);
    asm volatile("cp.async.wait_group 0;" ::: "memory");
    __syncthreads();

    const int wm = wid >> 2, wn = wid & 3;   // consumers: wm 0..2, wn 0..3
    const uint32_t a_base = (uint32_t)wm * (32 * 272)
                          + (uint32_t)(l & 15) * 272 + (uint32_t)(l >> 4) * 16;
    const uint32_t b_base = sb + S_OFF + (uint32_t)wn * (64 * 272)
                          + (uint32_t)(l >> 4) * (8 * 272)
                          + (uint32_t)(l & 7) * 272 + (uint32_t)((l >> 3) & 1) * 16;

    int parity = 0;
    for (int tile = blockIdx.x; tile < ntiles; tile += gridDim.x, parity ^= 1) {
        const int tok_base = tile * ROWS;

        if (producer) {
            int nt_tile = tile + gridDim.x;
            if (nt_tile < ntiles)
                stage_tile(smem, BUF_OFF + (parity ^ 1) * BUF_SZ,
                           BUF_OFF + (parity ^ 1) * BUF_SZ + 26112,
                           key, qry, nt_tile * ROWS, ntok, ptid);
        } else {
            const uint32_t koff = BUF_OFF + parity * BUF_SZ;
            const uint32_t qoff = koff + 26112;

            float acc[2][8][4];
            #pragma unroll
            for (int mt = 0; mt < 2; mt++)
                #pragma unroll
                for (int nt = 0; nt < 8; nt++)
                    #pragma unroll
                    for (int j = 0; j < 4; j++) acc[mt][nt][j] = 0.f;

            // ---- k-projection (pipelined) ----
            pass_pipe(sb + koff + a_base, b_base, acc);

            // ---- signs + near-zero flags ----
            unsigned long long sign = 0ull, flag = 0ull;
            #pragma unroll
            for (int mt = 0; mt < 2; mt++)
                #pragma unroll
                for (int nt = 0; nt < 8; nt++)
                    #pragma unroll
                    for (int j = 0; j < 4; j++) {
                        int id = mt * 32 + nt * 4 + j;
                        float v = acc[mt][nt][j];
                        if (v > 0.f) sign |= 1ull << id;
                        if (fabsf(v) < TAU) flag |= 1ull << id;
                    }

            // ---- warp-cooperative exact fp32 fixup ----
            for (;;) {
                uint32_t active = __ballot_sync(0xFFFFFFFFu, flag != 0ull);
                if (!active) break;
                int leader = __ffs(active) - 1;
                int tok = 0, proj = 0, id = 0;
                if (l == leader) {
                    id = __ffsll(flag) - 1;
                    int mt = id >> 5, j = id & 3;
                    int nt = (id >> 2) & 7;
                    int row = wm * 32 + mt * 16 + (l >> 2) + (j >> 1) * 8;
                    tok = tok_base + row; if (tok >= ntok) tok = ntok - 1;
                    proj = wn * 64 + nt * 8 + (l & 3) * 2 + (j & 1);
                }
                tok  = __shfl_sync(0xFFFFFFFFu, tok, leader);
                proj = __shfl_sync(0xFFFFFFFFu, proj, leader);
                const float* kr = key + (size_t)tok * 128 + l * 4;
                const float* sr = Sg + (size_t)proj * 128 + l * 4;
                float p = 0.f;
                #pragma unroll
                for (int d = 0; d < 4; d++) p = fmaf(__ldg(kr + d), __ldg(sr + d), p);
                #pragma unroll
                for (int off = 16; off > 0; off >>= 1)
                    p += __shfl_xor_sync(0xFFFFFFFFu, p, off);
                if (l == leader) {
                    unsigned long long b = 1ull << id;
                    if (p > 0.f) sign |= b; else sign &= ~b;
                    flag &= flag - 1;
                }
            }

            // ---- q-projection (pipelined) ----
            #pragma unroll
            for (int mt = 0; mt < 2; mt++)
                #pragma unroll
                for (int nt = 0; nt < 8; nt++)
                    #pragma unroll
                    for (int j = 0; j < 4; j++) acc[mt][nt][j] = 0.f;
            pass_pipe(sb + qoff + a_base, b_base, acc);

            // ---- epilogue: signed reduction, consumer-only barrier ----
            float* est = (float*)smem;   // [96][4]
            #pragma unroll
            for (int mt = 0; mt < 2; mt++)
                #pragma unroll
                for (int h = 0; h < 2; h++) {
                    float s = 0.f;
                    #pragma unroll
                    for (int nt = 0; nt < 8; nt++)
                        #pragma unroll
                        for (int jj = 0; jj < 2; jj++) {
                            int j = h * 2 + jj;
                            int id = mt * 32 + nt * 4 + j;
                            float v = acc[mt][nt][j];
                            s += ((sign >> id) & 1ull) ? v : -v;
                        }
                    s += __shfl_xor_sync(0xFFFFFFFFu, s, 1);
                    s += __shfl_xor_sync(0xFFFFFFFFu, s, 2);
                    if ((l & 3) == 0) {
                        int row = wm * 32 + mt * 16 + h * 8 + (l >> 2);
                        est[row * 4 + wn] = s;
                    }
                }
            asm volatile("bar.sync 1, %0;" :: "n"(NCONS) : "memory");
            if (tid < ROWS) {
                int tok = tok_base + tid;
                if (tok < ntok) {
                    const float* e = est + tid * 4;
                    out[tok] = SCALE * ((e[0] + e[1]) + (e[2] + e[3]));
                }
            }
        }
        __syncthreads();   // seal staged buffer / release est for next tile
    }
}

extern "C" void kernel_launch(void* const* d_in, const int* in_sizes, int n_in,
                              void* d_out, int out_size) {
    const float* q = (const float*)d_in[0];
    const float* k = (const float*)d_in[1];
    const float* S = (const float*)d_in[2];
    float* out = (float*)d_out;

    int ntok = in_sizes[0] / 128;
    int ntiles = (ntok + ROWS - 1) / ROWS;
    int grid = ntiles < 148 ? ntiles : 148;

    qjl_conv_S<<<16, 256>>>(S);

    cudaFuncSetAttribute(qjl_fused, cudaFuncAttributeMaxDynamicSharedMemorySize,
                         SMEM_TOTAL);
    qjl_fused<<<grid, THREADS, SMEM_TOTAL>>>(q, k, S, out, ntok, ntiles);
}

// round 14
// speedup vs baseline: 1.0494x; 1.0438x over previous
#include <cuda_runtime.h>
#include <cuda_fp16.h>
#include <cstdint>

#define THREADS 512
#define NCONS 384                      // 12 consumer warps
#define ROWS 96                        // tokens per tile
#define SCALE 0.0048957583488887505f   // sqrt(pi/2)/256
#define TAU 2e-2f

// smem layout (bytes). Row pitch 272B = 136 halves (conflict-free ldmatrix).
#define EST_OFF 0                      // float[96][4]
#define BUF_OFF 2048                   // 2 x (K 26112 + Q 26112)
#define BUF_SZ  52224
#define S_OFF   (BUF_OFF + 2 * BUF_SZ) // 106496; S: 256 x 272
#define SMEM_TOTAL (S_OFF + 69632)     // 176128

__device__ __align__(16) unsigned char g_Sfp16[69632];

__device__ __forceinline__ uint32_t smem_u32(const void* p) {
    uint32_t a;
    asm("{ .reg .u64 t; cvta.to.shared.u64 t, %1; cvt.u32.u64 %0, t; }"
        : "=r"(a) : "l"(p));
    return a;
}
__device__ __forceinline__ uint32_t f16x2(float lo, float hi) {
    uint32_t r;
    asm("cvt.rn.f16x2.f32 %0, %1, %2;" : "=r"(r) : "f"(hi), "f"(lo));
    return r;
}
__device__ __forceinline__ void ldsm_x4(uint32_t* r, uint32_t a) {
    asm volatile("ldmatrix.sync.aligned.m8n8.x4.shared.b16 {%0,%1,%2,%3}, [%4];"
                 : "=r"(r[0]), "=r"(r[1]), "=r"(r[2]), "=r"(r[3]) : "r"(a));
}
__device__ __forceinline__ void mma16816(float* d, const uint32_t* a,
                                         uint32_t b0, uint32_t b1) {
    asm volatile(
        "mma.sync.aligned.m16n8k16.row.col.f32.f16.f16.f32 "
        "{%0,%1,%2,%3}, {%4,%5,%6,%7}, {%8,%9}, {%0,%1,%2,%3};"
        : "+f"(d[0]), "+f"(d[1]), "+f"(d[2]), "+f"(d[3])
        : "r"(a[0]), "r"(a[1]), "r"(a[2]), "r"(a[3]), "r"(b0), "r"(b1));
}
__device__ __forceinline__ void cp16(uint32_t saddr, const void* gaddr) {
    asm volatile("cp.async.cg.shared.global [%0], [%1], 16;"
                 :: "r"(saddr), "l"(gaddr) : "memory");
}

// ---------------------------------------------------------------------------
// Kernel 0: convert S (256x128 fp32) -> fp16 image with 272B row pitch.
// ---------------------------------------------------------------------------
__global__ void qjl_conv_S(const float* __restrict__ S) {
    int i = blockIdx.x * blockDim.x + threadIdx.x;  // 0..4095
    int row = i >> 4, g = i & 15;
    const float4* src = (const float4*)(S + (size_t)row * 128 + g * 8);
    float4 a = __ldg(src), b = __ldg(src + 1);
    uint4 o;
    o.x = f16x2(a.x, a.y); o.y = f16x2(a.z, a.w);
    o.z = f16x2(b.x, b.y); o.w = f16x2(b.z, b.w);
    *(uint4*)(g_Sfp16 + row * 272 + g * 16) = o;
}

// ---------------------------------------------------------------------------
// stage one 96-token tile of k,q with 128 producer threads.
// MLP-pipelined: batch b+1's 8 LDG.128 are issued BEFORE batch b's
// convert/store, keeping ~8-16 loads in flight per thread.
// 24 float4-pairs per thread = 6 batches of 4.
// ---------------------------------------------------------------------------
__device__ __forceinline__ void stage_tile(char* smem, uint32_t koff, uint32_t qoff,
                                           const float* __restrict__ key,
                                           const float* __restrict__ qry,
                                           int tok_base, int ntok, int ptid) {
    if (tok_base + ROWS <= ntok) {
        const float4* kg = (const float4*)(key + (size_t)tok_base * 128) + ptid;
        const float4* qg = (const float4*)(qry + (size_t)tok_base * 128) + ptid;
        float4 vk[2][4], vq[2][4];
        #pragma unroll
        for (int i = 0; i < 4; i++) {
            vk[0][i] = __ldg(kg + i * 128);
            vq[0][i] = __ldg(qg + i * 128);
        }
        #pragma unroll
        for (int b = 0; b < 6; b++) {
            const int cur = b & 1, nxt = cur ^ 1;
            if (b < 5) {
                #pragma unroll
                for (int i = 0; i < 4; i++) {
                    vk[nxt][i] = __ldg(kg + ((b + 1) * 4 + i) * 128);
                    vq[nxt][i] = __ldg(qg + ((b + 1) * 4 + i) * 128);
                }
            }
            #pragma unroll
            for (int i = 0; i < 4; i++) {
                int u = ptid + (b * 4 + i) * 128;
                uint32_t doff = (uint32_t)(u >> 5) * 272 + (uint32_t)(u & 31) * 8;
                uint2 pk; pk.x = f16x2(vk[cur][i].x, vk[cur][i].y);
                          pk.y = f16x2(vk[cur][i].z, vk[cur][i].w);
                *(uint2*)(smem + koff + doff) = pk;
                uint2 pq; pq.x = f16x2(vq[cur][i].x, vq[cur][i].y);
                          pq.y = f16x2(vq[cur][i].z, vq[cur][i].w);
                *(uint2*)(smem + qoff + doff) = pq;
            }
        }
    } else {
        for (int u = ptid; u < ROWS * 32; u += 128) {
            int row = u >> 5, c4 = u & 31;
            int tok = tok_base + row; if (tok >= ntok) tok = ntok - 1;
            uint32_t doff = (uint32_t)row * 272 + (uint32_t)c4 * 8;
            float4 v = __ldg((const float4*)(key + (size_t)tok * 128) + c4);
            uint2 pk; pk.x = f16x2(v.x, v.y); pk.y = f16x2(v.z, v.w);
            *(uint2*)(smem + koff + doff) = pk;
            float4 w = __ldg((const float4*)(qry + (size_t)tok * 128) + c4);
            uint2 pq; pq.x = f16x2(w.x, w.y); pq.y = f16x2(w.z, w.w);
            *(uint2*)(smem + qoff + doff) = pq;
        }
    }
}

// ---------------------------------------------------------------------------
// Main kernel: persistent, 1 CTA/SM. 12 consumer warps (3Mx4N, 32x64 tiles)
// compute tile i while 4 producer warps stage tile i+1 (double-buffered).
// ---------------------------------------------------------------------------
__global__ void __launch_bounds__(THREADS, 1)
qjl_fused(const float* __restrict__ qry, const float* __restrict__ key,
          const float* __restrict__ Sg, float* __restrict__ out,
          int ntok, int ntiles) {
    extern __shared__ char smem[];
    const uint32_t sb = smem_u32(smem);
    const int tid = threadIdx.x, wid = tid >> 5, l = tid & 31;
    const bool producer = (wid >= 12);
    const int ptid = tid - NCONS;

    // ---- S image -> smem (all threads, async) ----
    for (int u = tid; u < 4352; u += THREADS)
        cp16(sb + S_OFF + u * 16, g_Sfp16 + u * 16);
    asm volatile("cp.async.commit_group;" ::: "memory");

    // ---- prologue: producers stage first tile into buffer 0 ----
    if (producer)
        stage_tile(smem, BUF_OFF, BUF_OFF + 26112, key, qry,
                   blockIdx.x * ROWS, ntok, ptid);
    asm volatile("cp.async.wait_group 0;" ::: "memory");
    __syncthreads();

    const int wm = wid >> 2, wn = wid & 3;   // consumers: wm 0..2, wn 0..3
    const uint32_t a_base = (uint32_t)wm * (32 * 272)
                          + (uint32_t)(l & 15) * 272 + (uint32_t)(l >> 4) * 16;
    const uint32_t b_base = sb + S_OFF + (uint32_t)wn * (64 * 272)
                          + (uint32_t)(l >> 4) * (8 * 272)
                          + (uint32_t)(l & 7) * 272 + (uint32_t)((l >> 3) & 1) * 16;

    int parity = 0;
    for (int tile = blockIdx.x; tile < ntiles; tile += gridDim.x, parity ^= 1) {
        const int tok_base = tile * ROWS;

        if (producer) {
            int nt_tile = tile + gridDim.x;
            if (nt_tile < ntiles)
                stage_tile(smem, BUF_OFF + (parity ^ 1) * BUF_SZ,
                           BUF_OFF + (parity ^ 1) * BUF_SZ + 26112,
                           key, qry, nt_tile * ROWS, ntok, ptid);
        } else {
            const uint32_t koff = BUF_OFF + parity * BUF_SZ;
            const uint32_t qoff = koff + 26112;

            float acc[2][8][4];
            #pragma unroll
            for (int mt = 0; mt < 2; mt++)
                #pragma unroll
                for (int nt = 0; nt < 8; nt++)
                    #pragma unroll
                    for (int j = 0; j < 4; j++) acc[mt][nt][j] = 0.f;

            // ---- k-projection ----
            #pragma unroll
            for (int ks = 0; ks < 8; ks++) {
                uint32_t aaddr = sb + koff + a_base + ks * 32;
                uint32_t A0[4], A1[4];
                ldsm_x4(A0, aaddr);
                ldsm_x4(A1, aaddr + 16 * 272);
                #pragma unroll
                for (int g = 0; g < 4; g++) {
                    uint32_t B[4];
                    ldsm_x4(B, b_base + g * (16 * 272) + ks * 32);
                    mma16816(acc[0][2 * g],     A0, B[0], B[1]);
                    mma16816(acc[1][2 * g],     A1, B[0], B[1]);
                    mma16816(acc[0][2 * g + 1], A0, B[2], B[3]);
                    mma16816(acc[1][2 * g + 1], A1, B[2], B[3]);
                }
            }

            // ---- signs + near-zero flags ----
            unsigned long long sign = 0ull, flag = 0ull;
            #pragma unroll
            for (int mt = 0; mt < 2; mt++)
                #pragma unroll
                for (int nt = 0; nt < 8; nt++)
                    #pragma unroll
                    for (int j = 0; j < 4; j++) {
                        int id = mt * 32 + nt * 4 + j;
                        float v = acc[mt][nt][j];
                        if (v > 0.f) sign |= 1ull << id;
                        if (fabsf(v) < TAU) flag |= 1ull << id;
                    }

            // ---- warp-cooperative exact fp32 fixup ----
            for (;;) {
                uint32_t active = __ballot_sync(0xFFFFFFFFu, flag != 0ull);
                if (!active) break;
                int leader = __ffs(active) - 1;
                int tok = 0, proj = 0, id = 0;
                if (l == leader) {
                    id = __ffsll(flag) - 1;
                    int mt = id >> 5, j = id & 3;
                    int nt = (id >> 2) & 7;
                    int row = wm * 32 + mt * 16 + (l >> 2) + (j >> 1) * 8;
                    tok = tok_base + row; if (tok >= ntok) tok = ntok - 1;
                    proj = wn * 64 + nt * 8 + (l & 3) * 2 + (j & 1);
                }
                tok  = __shfl_sync(0xFFFFFFFFu, tok, leader);
                proj = __shfl_sync(0xFFFFFFFFu, proj, leader);
                const float* kr = key + (size_t)tok * 128 + l * 4;
                const float* sr = Sg + (size_t)proj * 128 + l * 4;
                float p = 0.f;
                #pragma unroll
                for (int d = 0; d < 4; d++) p = fmaf(__ldg(kr + d), __ldg(sr + d), p);
                #pragma unroll
                for (int off = 16; off > 0; off >>= 1)
                    p += __shfl_xor_sync(0xFFFFFFFFu, p, off);
                if (l == leader) {
                    unsigned long long b = 1ull << id;
                    if (p > 0.f) sign |= b; else sign &= ~b;
                    flag &= flag - 1;
                }
            }

            // ---- q-projection ----
            #pragma unroll
            for (int mt = 0; mt < 2; mt++)
                #pragma unroll
                for (int nt = 0; nt < 8; nt++)
                    #pragma unroll
                    for (int j = 0; j < 4; j++) acc[mt][nt][j] = 0.f;
            #pragma unroll
            for (int ks = 0; ks < 8; ks++) {
                uint32_t aaddr = sb + qoff + a_base + ks * 32;
                uint32_t A0[4], A1[4];
                ldsm_x4(A0, aaddr);
                ldsm_x4(A1, aaddr + 16 * 272);
                #pragma unroll
                for (int g = 0; g < 4; g++) {
                    uint32_t B[4];
                    ldsm_x4(B, b_base + g * (16 * 272) + ks * 32);
                    mma16816(acc[0][2 * g],     A0, B[0], B[1]);
                    mma16816(acc[1][2 * g],     A1, B[0], B[1]);
                    mma16816(acc[0][2 * g + 1], A0, B[2], B[3]);
                    mma16816(acc[1][2 * g + 1], A1, B[2], B[3]);
                }
            }

            // ---- epilogue: signed reduction, consumer-only barrier ----
            float* est = (float*)smem;   // [96][4]
            #pragma unroll
            for (int mt = 0; mt < 2; mt++)
                #pragma unroll
                for (int h = 0; h < 2; h++) {
                    float s = 0.f;
                    #pragma unroll
                    for (int nt = 0; nt < 8; nt++)
                        #pragma unroll
                        for (int jj = 0; jj < 2; jj++) {
                            int j = h * 2 + jj;
                            int id = mt * 32 + nt * 4 + j;
                            float v = acc[mt][nt][j];
                            s += ((sign >> id) & 1ull) ? v : -v;
                        }
                    s += __shfl_xor_sync(0xFFFFFFFFu, s, 1);
                    s += __shfl_xor_sync(0xFFFFFFFFu, s, 2);
                    if ((l & 3) == 0) {
                        int row = wm * 32 + mt * 16 + h * 8 + (l >> 2);
                        est[row * 4 + wn] = s;
                    }
                }
            asm volatile("bar.sync 1, %0;" :: "n"(NCONS) : "memory");
            if (tid < ROWS) {
                int tok = tok_base + tid;
                if (tok < ntok) {
                    const float* e = est + tid * 4;
                    out[tok] = SCALE * ((e[0] + e[1]) + (e[2] + e[3]));
                }
            }
        }
        __syncthreads();   // seal staged buffer / release est for next tile
    }
}

extern "C" void kernel_launch(void* const* d_in, const int* in_sizes, int n_in,
                              void* d_out, int out_size) {
    const float* q = (const float*)d_in[0];
    const float* k = (const float*)d_in[1];
    const float* S = (const float*)d_in[2];
    float* out = (float*)d_out;

    int ntok = in_sizes[0] / 128;
    int ntiles = (ntok + ROWS - 1) / ROWS;
    int grid = ntiles < 148 ? ntiles : 148;

    qjl_conv_S<<<16, 256>>>(S);

    cudaFuncSetAttribute(qjl_fused, cudaFuncAttributeMaxDynamicSharedMemorySize,
                         SMEM_TOTAL);
    qjl_fused<<<grid, THREADS, SMEM_TOTAL>>>(q, k, S, out, ntok, ntiles);
}